// round 5
// baseline (speedup 1.0000x reference)
#include <cuda_runtime.h>
#include <math.h>

typedef unsigned long long ull;

// Problem constants
#define BB  4
#define TT  16
#define HH  64
#define WW  64
#define CIN 32
#define FF  64   // per-gate channels; 4*FF = 256 gate channels

// Packed weights: per (k,ci,f): [0]=pack(w_i,w_f), [1]=pack(w_c,w_o)
__device__ ull   g_Wh2[9 * 64 * 64 * 2];   // 589KB
__device__ ull   g_Wx2[9 * 32 * 64 * 2];   // 294KB
__device__ float4 g_br[64];                // bias per f: {b_i,b_f,b_c,b_o}
__device__ float g_h[2][BB * HH * WW * FF];  // ping-pong hidden state, NHWC
__device__ float g_c[BB * HH * WW * FF];     // cell state, NHWC

__device__ __forceinline__ ull pack2(float lo, float hi) {
    ull r; asm("mov.b64 %0, {%1, %2};" : "=l"(r) : "f"(lo), "f"(hi)); return r;
}
__device__ __forceinline__ float2 unpack2(ull v) {
    float2 r; asm("mov.b64 {%0, %1}, %2;" : "=f"(r.x), "=f"(r.y) : "l"(v)); return r;
}
#define FMA2(d, a, b) asm("fma.rn.f32x2 %0, %1, %2, %0;" : "+l"(d) : "l"(a), "l"(b))

// ---------------------------------------------------------------------------
// Reorder weights into gate-pair-packed f32x2 layout.
//   g_Wh2[((k*64+ci)*64+f)*2 + 0] = pack(Wh[k][ci][0*64+f], Wh[k][ci][1*64+f])
//   g_Wh2[((k*64+ci)*64+f)*2 + 1] = pack(Wh[k][ci][2*64+f], Wh[k][ci][3*64+f])
// ---------------------------------------------------------------------------
__global__ void reorder_kernel(const float* __restrict__ Wx,
                               const float* __restrict__ Wh,
                               const float* __restrict__ b)
{
    const int NH = 9 * 64 * 64;   // (k,ci,f) triples for Wh
    const int NX = 9 * 32 * 64;
    int idx = blockIdx.x * blockDim.x + threadIdx.x;
    if (idx < NH) {
        int f = idx & 63, kci = idx >> 6;
        const float* s = Wh + kci * 256 + f;
        g_Wh2[idx * 2 + 0] = pack2(s[0],   s[64]);
        g_Wh2[idx * 2 + 1] = pack2(s[128], s[192]);
    } else if (idx < NH + NX) {
        int j = idx - NH;
        int f = j & 63, kci = j >> 6;
        const float* s = Wx + kci * 256 + f;
        g_Wx2[j * 2 + 0] = pack2(s[0],   s[64]);
        g_Wx2[j * 2 + 1] = pack2(s[128], s[192]);
    } else if (idx < NH + NX + 64) {
        int f = idx - NH - NX;
        g_br[f] = make_float4(b[f], b[64 + f], b[128 + f], b[192 + f]);
    }
}

// Zero h ping buffer 0 and c each launch -> graph replays deterministic.
__global__ void zero_kernel()
{
    int i = blockIdx.x * blockDim.x + threadIdx.x;
    if (i < BB * HH * WW * FF) { g_h[0][i] = 0.f; g_c[i] = 0.f; }
}

// ---------------------------------------------------------------------------
// One fused ConvLSTM timestep with f32x2 packed math.
// Block: 8x8 spatial tile x 64 f-channels, 256 threads.
// tid = pg*64 + f ; pg in 0..3 owns 2 rows (16 pixels).
// Accumulators: per pixel, acc_if = (z_i, z_f) and acc_co = (z_c, z_o) as f32x2.
// h/x tiles stored VALUE-DUPLICATED in smem so one LDS.128 gives two (v,v)
// f32x2 operands directly (no per-scalar MOV packing).
// ---------------------------------------------------------------------------
__global__ __launch_bounds__(256, 2)
void step_kernel(const float* __restrict__ x,
                 const float* __restrict__ Wp,
                 const float* __restrict__ bp,
                 float* __restrict__ out,
                 int t)
{
    extern __shared__ float smem[];
    float* shd_h = smem;                  // [10*10][128] duplicated: 51.2KB
    float* shd_x = smem + 100 * 128;      // [10*10][64]  duplicated: 25.6KB

    const int bI  = blockIdx.z;
    const int tx0 = blockIdx.x * 8;
    const int ty0 = blockIdx.y * 8;
    const int tid = threadIdx.x;
    const int f   = tid & 63;
    const int pg  = tid >> 6;
    const int pr0 = pg * 2;

    const float* __restrict__ hin  = g_h[t & 1];
    float*       __restrict__ hout = g_h[(t + 1) & 1];

    // --- load h tile, value-duplicated (zero-padded halo) ---
    for (int s = tid; s < 100 * 64; s += 256) {
        int ci = s & 63, sp = s >> 6;
        int rx = sp % 10, ry = sp / 10;
        int gy = ty0 - 1 + ry, gx = tx0 - 1 + rx;
        float v = 0.f;
        if ((unsigned)gy < 64u && (unsigned)gx < 64u)
            v = hin[((bI * 64 + gy) * 64 + gx) * 64 + ci];
        shd_h[sp * 128 + 2 * ci]     = v;
        shd_h[sp * 128 + 2 * ci + 1] = v;
    }
    // --- load x tile, value-duplicated ---
    const float* __restrict__ xt = x + (size_t)(bI * TT + t) * (HH * WW * CIN);
    for (int s = tid; s < 100 * 32; s += 256) {
        int ci = s & 31, sp = s >> 5;
        int rx = sp % 10, ry = sp / 10;
        int gy = ty0 - 1 + ry, gx = tx0 - 1 + rx;
        float v = 0.f;
        if ((unsigned)gy < 64u && (unsigned)gx < 64u)
            v = xt[(gy * 64 + gx) * 32 + ci];
        shd_x[sp * 64 + 2 * ci]     = v;
        shd_x[sp * 64 + 2 * ci + 1] = v;
    }
    __syncthreads();

    // --- accumulators: 16 pixels x {(i,f),(c,o)} ---
    ull acc_if[16], acc_co[16];
    {
        float4 bias = g_br[f];
        ull bif = pack2(bias.x, bias.y);
        ull bco = pack2(bias.z, bias.w);
#pragma unroll
        for (int p = 0; p < 16; ++p) { acc_if[p] = bif; acc_co[p] = bco; }
    }

    // --- recurrent conv: h (ci = 64) ---
    for (int k = 0; k < 9; ++k) {
        const int dy = k / 3, dx = k - dy * 3;
        const ull* __restrict__ wb = g_Wh2 + ((size_t)(k * 64) * 64 + f) * 2;
        const float* __restrict__ hb = shd_h + ((pr0 + dy) * 10 + dx) * 128;
#pragma unroll 2
        for (int c4 = 0; c4 < 16; ++c4) {          // 4 ci per iter
            ull wif0, wco0, wif1, wco1, wif2, wco2, wif3, wco3;
            {
                ulonglong2 w0 = *(const ulonglong2*)(wb + (size_t)(c4 * 4 + 0) * 128);
                ulonglong2 w1 = *(const ulonglong2*)(wb + (size_t)(c4 * 4 + 1) * 128);
                ulonglong2 w2 = *(const ulonglong2*)(wb + (size_t)(c4 * 4 + 2) * 128);
                ulonglong2 w3 = *(const ulonglong2*)(wb + (size_t)(c4 * 4 + 3) * 128);
                wif0 = w0.x; wco0 = w0.y; wif1 = w1.x; wco1 = w1.y;
                wif2 = w2.x; wco2 = w2.y; wif3 = w3.x; wco3 = w3.y;
            }
#pragma unroll
            for (int r = 0; r < 2; ++r)
#pragma unroll
                for (int cx = 0; cx < 8; ++cx) {
                    const float* hp = hb + (r * 10 + cx) * 128 + c4 * 8;
                    ulonglong2 a0 = *(const ulonglong2*)(hp);      // (v0,v0),(v1,v1)
                    ulonglong2 a1 = *(const ulonglong2*)(hp + 4);  // (v2,v2),(v3,v3)
                    const int p = r * 8 + cx;
                    FMA2(acc_if[p], a0.x, wif0); FMA2(acc_co[p], a0.x, wco0);
                    FMA2(acc_if[p], a0.y, wif1); FMA2(acc_co[p], a0.y, wco1);
                    FMA2(acc_if[p], a1.x, wif2); FMA2(acc_co[p], a1.x, wco2);
                    FMA2(acc_if[p], a1.y, wif3); FMA2(acc_co[p], a1.y, wco3);
                }
        }
    }

    // --- input conv: x (ci = 32) ---
    for (int k = 0; k < 9; ++k) {
        const int dy = k / 3, dx = k - dy * 3;
        const ull* __restrict__ wb = g_Wx2 + ((size_t)(k * 32) * 64 + f) * 2;
        const float* __restrict__ xb = shd_x + ((pr0 + dy) * 10 + dx) * 64;
#pragma unroll 2
        for (int c4 = 0; c4 < 8; ++c4) {
            ull wif0, wco0, wif1, wco1, wif2, wco2, wif3, wco3;
            {
                ulonglong2 w0 = *(const ulonglong2*)(wb + (size_t)(c4 * 4 + 0) * 128);
                ulonglong2 w1 = *(const ulonglong2*)(wb + (size_t)(c4 * 4 + 1) * 128);
                ulonglong2 w2 = *(const ulonglong2*)(wb + (size_t)(c4 * 4 + 2) * 128);
                ulonglong2 w3 = *(const ulonglong2*)(wb + (size_t)(c4 * 4 + 3) * 128);
                wif0 = w0.x; wco0 = w0.y; wif1 = w1.x; wco1 = w1.y;
                wif2 = w2.x; wco2 = w2.y; wif3 = w3.x; wco3 = w3.y;
            }
#pragma unroll
            for (int r = 0; r < 2; ++r)
#pragma unroll
                for (int cx = 0; cx < 8; ++cx) {
                    const float* xp = xb + (r * 10 + cx) * 64 + c4 * 8;
                    ulonglong2 a0 = *(const ulonglong2*)(xp);
                    ulonglong2 a1 = *(const ulonglong2*)(xp + 4);
                    const int p = r * 8 + cx;
                    FMA2(acc_if[p], a0.x, wif0); FMA2(acc_co[p], a0.x, wco0);
                    FMA2(acc_if[p], a0.y, wif1); FMA2(acc_co[p], a0.y, wco1);
                    FMA2(acc_if[p], a1.x, wif2); FMA2(acc_co[p], a1.x, wco2);
                    FMA2(acc_if[p], a1.y, wif3); FMA2(acc_co[p], a1.y, wco3);
                }
        }
    }

    // --- gates + state update ---
    float hn[16];
#pragma unroll
    for (int p = 0; p < 16; ++p) {
        int py = ty0 + pr0 + (p >> 3);
        int px = tx0 + (p & 7);
        int cidx = ((bI * 64 + py) * 64 + px) * 64 + f;
        float2 zif = unpack2(acc_if[p]);
        float2 zco = unpack2(acc_co[p]);
        float ig = __saturatef(fmaf(0.2f, zif.x, 0.5f));
        float fg = __saturatef(fmaf(0.2f, zif.y, 0.5f));
        float og = __saturatef(fmaf(0.2f, zco.y, 0.5f));
        float cn = fmaf(fg, g_c[cidx], ig * tanhf(zco.x));
        g_c[cidx] = cn;
        float hv = og * tanhf(cn);
        hout[cidx] = hv;
        hn[p] = hv;
    }

    // --- residual 1x1 projection (x tile already in smem, duplicated layout) ---
    float res[16];
    {
        float bpf = __ldg(bp + f);
#pragma unroll
        for (int p = 0; p < 16; ++p) res[p] = bpf;
    }
#pragma unroll 2
    for (int ci = 0; ci < 32; ++ci) {
        float wv = __ldg(Wp + ci * 64 + f);
#pragma unroll
        for (int r = 0; r < 2; ++r)
#pragma unroll
            for (int cx = 0; cx < 8; ++cx) {
                float xv = shd_x[((pr0 + 1 + r) * 10 + (cx + 1)) * 64 + 2 * ci];
                res[r * 8 + cx] = fmaf(xv, wv, res[r * 8 + cx]);
            }
    }

    // --- write output ---
    float* __restrict__ op = out + (size_t)(bI * TT + t) * 4096 * 64;
#pragma unroll
    for (int p = 0; p < 16; ++p) {
        int py = ty0 + pr0 + (p >> 3);
        int px = tx0 + (p & 7);
        op[(py * 64 + px) * 64 + f] = hn[p] + res[p];
    }
}

// ---------------------------------------------------------------------------
extern "C" void kernel_launch(void* const* d_in, const int* in_sizes, int n_in,
                              void* d_out, int out_size)
{
    const float* x  = (const float*)d_in[0];
    const float* Wx = (const float*)d_in[1];
    const float* Wh = (const float*)d_in[2];
    const float* b  = (const float*)d_in[3];
    const float* Wp = (const float*)d_in[4];
    const float* bp = (const float*)d_in[5];
    float* out = (float*)d_out;

    const int SMEM_BYTES = (100 * 128 + 100 * 64) * 4;   // 76800
    cudaFuncSetAttribute(step_kernel,
                         cudaFuncAttributeMaxDynamicSharedMemorySize, SMEM_BYTES);

    const int nre = 9 * 64 * 64 + 9 * 32 * 64 + 64;
    reorder_kernel<<<(nre + 255) / 256, 256>>>(Wx, Wh, b);

    const int nz = BB * HH * WW * FF;
    zero_kernel<<<(nz + 255) / 256, 256>>>();

    dim3 grid(8, 8, BB);
    for (int t = 0; t < TT; ++t)
        step_kernel<<<grid, 256, SMEM_BYTES>>>(x, Wp, bp, out, t);
}

// round 7
// speedup vs baseline: 3.3533x; 3.3533x over previous
#include <cuda_runtime.h>
#include <cuda_bf16.h>
#include <cstdint>
#include <math.h>

#define BBATCH 4
#define TT   16
#define PPX  4356          // 66*66 padded pixels
#define GRD  192           // guard pixels at both ends of padded arrays
#define NTOT ((2*GRD + BBATCH*PPX) * 64)
#define XTOT ((2*GRD + BBATCH*TT*PPX) * 32)
#define NC   (BBATCH * PPX * 64)

// ---------------- static device state ----------------
__device__ __nv_bfloat16 g_h_hi[2][NTOT];
__device__ __nv_bfloat16 g_h_lo[2][NTOT];
__device__ float         g_c[NC];
__device__ __nv_bfloat16 g_x_hi[XTOT];
__device__ __nv_bfloat16 g_x_lo[XTOT];
// mma.sync B fragments, lane-ordered:
// Wh: [tap(9)][plane(2)][chunk(4)][ntile(32)][lane(32)] -> uint2 {b0,b1}
// Wx: [tap(9)][plane(2)][chunk(2)][ntile(32)][lane(32)]
__device__ uint2 g_WhF[9 * 2 * 4 * 32 * 32];
__device__ uint2 g_WxF[9 * 2 * 2 * 32 * 32];

// ---------------- helpers ----------------
__device__ __forceinline__ uint32_t smem_u32(const void* p) {
    uint32_t a;
    asm("{ .reg .u64 t; cvta.to.shared.u64 t, %1; cvt.u32.u64 %0, t; }" : "=r"(a) : "l"(p));
    return a;
}

#define LDMX4(r, addr) \
    asm volatile("ldmatrix.sync.aligned.m8n8.x4.shared.b16 {%0,%1,%2,%3}, [%4];" \
        : "=r"((r)[0]), "=r"((r)[1]), "=r"((r)[2]), "=r"((r)[3]) : "r"(addr))

#define MMA_BF16(d, a, bf) \
    asm volatile("mma.sync.aligned.m16n8k16.row.col.f32.bf16.bf16.f32 " \
        "{%0,%1,%2,%3}, {%4,%5,%6,%7}, {%8,%9}, {%0,%1,%2,%3};" \
        : "+f"((d)[0]), "+f"((d)[1]), "+f"((d)[2]), "+f"((d)[3]) \
        : "r"((a)[0]), "r"((a)[1]), "r"((a)[2]), "r"((a)[3]), "r"((bf).x), "r"((bf).y))

__device__ __forceinline__ uint32_t enc_bf(float v, int plane) {
    __nv_bfloat16 h = __float2bfloat16(v);
    if (plane) h = __float2bfloat16(v - __bfloat162float(h));
    return (uint32_t)__bfloat16_as_ushort(h);
}

// ---------------- prep kernels ----------------
__global__ void zero_kernel() {
    int i = blockIdx.x * blockDim.x + threadIdx.x;
    if (i < NTOT) {
        g_h_hi[0][i] = __float2bfloat16(0.f); g_h_hi[1][i] = __float2bfloat16(0.f);
        g_h_lo[0][i] = __float2bfloat16(0.f); g_h_lo[1][i] = __float2bfloat16(0.f);
    }
    if (i < NC) g_c[i] = 0.f;
}

__global__ void pad_x_kernel(const float* __restrict__ x) {
    long i = (long)blockIdx.x * blockDim.x + threadIdx.x;
    if (i >= XTOT) return;
    int ci = (int)(i & 31);
    long p = i >> 5;
    float v = 0.f;
    if (p >= GRD && p < GRD + (long)BBATCH * TT * PPX) {
        long pp = p - GRD;
        int bt = (int)(pp / PPX), q = (int)(pp % PPX);
        int py = q / 66, px = q % 66;
        if (py >= 1 && py <= 64 && px >= 1 && px <= 64)
            v = x[(((long)bt * 4096) + (py - 1) * 64 + (px - 1)) * 32 + ci];
    }
    __nv_bfloat16 h = __float2bfloat16(v);
    g_x_hi[i] = h;
    g_x_lo[i] = __float2bfloat16(v - __bfloat162float(h));
}

__global__ void prep_w_kernel(const float* __restrict__ Wx, const float* __restrict__ Wh) {
    int idx = blockIdx.x * blockDim.x + threadIdx.x;
    if (idx < 73728) {                    // Wh fragments
        int tap   = idx >> 13;
        int r     = idx & 8191;
        int plane = r >> 12;
        int r2    = r & 4095;
        int chunk = r2 >> 10;
        int r3    = r2 & 1023;
        int nt    = r3 >> 5, lane = r3 & 31;
        int k0 = chunk * 16 + (lane & 3) * 2;
        int n  = nt * 8 + (lane >> 2);
        const float* W = Wh;
        float v00 = W[((size_t)tap * 64 + k0    ) * 256 + n];
        float v01 = W[((size_t)tap * 64 + k0 + 1) * 256 + n];
        float v10 = W[((size_t)tap * 64 + k0 + 8) * 256 + n];
        float v11 = W[((size_t)tap * 64 + k0 + 9) * 256 + n];
        uint2 o;
        o.x = enc_bf(v00, plane) | (enc_bf(v01, plane) << 16);
        o.y = enc_bf(v10, plane) | (enc_bf(v11, plane) << 16);
        g_WhF[idx] = o;
    } else if (idx < 73728 + 36864) {     // Wx fragments
        int j     = idx - 73728;
        int tap   = j >> 12;
        int r     = j & 4095;
        int plane = r >> 11;
        int r2    = r & 2047;
        int chunk = r2 >> 10;
        int r3    = r2 & 1023;
        int nt    = r3 >> 5, lane = r3 & 31;
        int k0 = chunk * 16 + (lane & 3) * 2;
        int n  = nt * 8 + (lane >> 2);
        const float* W = Wx;
        float v00 = W[((size_t)tap * 32 + k0    ) * 256 + n];
        float v01 = W[((size_t)tap * 32 + k0 + 1) * 256 + n];
        float v10 = W[((size_t)tap * 32 + k0 + 8) * 256 + n];
        float v11 = W[((size_t)tap * 32 + k0 + 9) * 256 + n];
        uint2 o;
        o.x = enc_bf(v00, plane) | (enc_bf(v01, plane) << 16);
        o.y = enc_bf(v10, plane) | (enc_bf(v11, plane) << 16);
        g_WxF[j] = o;
    }
}

__global__ void residual_kernel(const float* __restrict__ x, const float* __restrict__ Wp,
                                const float* __restrict__ bp, float* __restrict__ out) {
    long gid = (long)blockIdx.x * blockDim.x + threadIdx.x;   // (b,t,px)*64 + f
    int f = (int)(gid & 63);
    long btp = gid >> 6;
    const float* xp = x + btp * 32;
    float acc = __ldg(bp + f);
#pragma unroll
    for (int ci = 0; ci < 32; ++ci)
        acc = fmaf(__ldg(xp + ci), __ldg(Wp + ci * 64 + f), acc);
    out[gid] = acc;
}

// ---------------- fused ConvLSTM step (mma.sync bf16) ----------------
// smem layout (bytes):
//   phase 1 (conv):   [0      : 37728) h_hi slab  262 rows x 144B
//                     [37728  : 75456) h_lo slab
//                     [75456  : 96416) x_hi slab  262 rows x 80B
//                     [96416  :117376) x_lo slab
//   phase 2 (epilog): [0      :133120) z[128][260] fp32  (aliases slabs)
//   always:           [133120 :134144) bias[256] fp32
#define SM_SHH   0
#define SM_SHL   37728
#define SM_SXH   75456
#define SM_SXL   96416
#define SM_BIAS  133120
#define SM_TOTAL 134144

__global__ void __launch_bounds__(512, 1)
step_kernel(const float* __restrict__ bias, float* __restrict__ out, int t)
{
    extern __shared__ __align__(16) char smem[];
    float* zs = (float*)smem;
    float* bs = (float*)(smem + SM_BIAS);

    const int tid  = threadIdx.x;
    const int lane = tid & 31;
    const int wid  = tid >> 5;      // 0..15
    const int wm   = wid & 1;       // M half (64 rows)
    const int wn   = wid >> 1;      // 0..7, N group of 32
    const int b    = blockIdx.y;
    const int q0   = blockIdx.x * 128;
    const int bt   = b * TT + t;

    if (tid < 256) bs[tid] = bias[tid];

    // ---- load slabs (padded rows q0-67 .. q0+194) ----
    {
        long off = (long)GRD * 64 + ((long)b * PPX + q0 - 67) * 64;
        const uint4* sh = (const uint4*)(g_h_hi[t & 1] + off);
        const uint4* sl = (const uint4*)(g_h_lo[t & 1] + off);
        for (int i = tid; i < 2096; i += 512) {
            int r = i >> 3, c = i & 7;
            *(uint4*)(smem + SM_SHH + r * 144 + c * 16) = sh[i];
            *(uint4*)(smem + SM_SHL + r * 144 + c * 16) = sl[i];
        }
        long offx = (long)GRD * 32 + ((long)bt * PPX + q0 - 67) * 32;
        const uint4* xh = (const uint4*)(g_x_hi + offx);
        const uint4* xl = (const uint4*)(g_x_lo + offx);
        for (int i = tid; i < 1048; i += 512) {
            int r = i >> 2, c = i & 3;
            *(uint4*)(smem + SM_SXH + r * 80 + c * 16) = xh[i];
            *(uint4*)(smem + SM_SXL + r * 80 + c * 16) = xl[i];
        }
    }
    __syncthreads();

    float acc[4][4][4];
#pragma unroll
    for (int mt = 0; mt < 4; ++mt)
#pragma unroll
        for (int nt = 0; nt < 4; ++nt)
#pragma unroll
            for (int e = 0; e < 4; ++e) acc[mt][nt][e] = 0.f;

    const uint32_t shh_u = smem_u32(smem + SM_SHH);
    const uint32_t shl_u = smem_u32(smem + SM_SHL);
    const uint32_t sxh_u = smem_u32(smem + SM_SXH);
    const uint32_t sxl_u = smem_u32(smem + SM_SXL);
    const int rowA = lane & 15;
    const int colh = (lane >> 4) * 16;

    // ---- h taps: 9 x (K=64, 4 k16-chunks) x 3 products ----
    for (int tap = 0; tap < 9; ++tap) {
        const int shift = (tap / 3) * 66 + (tap % 3);
        const uint32_t ah_base = shh_u + (uint32_t)(shift + wm * 64 + rowA) * 144 + colh;
        const uint32_t al_base = shl_u + (uint32_t)(shift + wm * 64 + rowA) * 144 + colh;
        for (int chunk = 0; chunk < 4; ++chunk) {
            const uint2* ph = g_WhF + (size_t)(tap * 8 + chunk) * 1024 + wn * 128 + lane;
            const uint2* pl = ph + 4096;
            uint2 bh[4], bl[4];
#pragma unroll
            for (int nt = 0; nt < 4; ++nt) { bh[nt] = ph[nt * 32]; bl[nt] = pl[nt * 32]; }
#pragma unroll
            for (int mt = 0; mt < 4; ++mt) {
                uint32_t ah[4], al[4];
                LDMX4(ah, ah_base + mt * (16 * 144) + chunk * 32);
                LDMX4(al, al_base + mt * (16 * 144) + chunk * 32);
#pragma unroll
                for (int nt = 0; nt < 4; ++nt) {
                    MMA_BF16(acc[mt][nt], ah, bh[nt]);
                    MMA_BF16(acc[mt][nt], al, bh[nt]);
                    MMA_BF16(acc[mt][nt], ah, bl[nt]);
                }
            }
        }
    }

    // ---- x taps: 9 x (K=32, 2 k16-chunks) x 3 products ----
    for (int tap = 0; tap < 9; ++tap) {
        const int shift = (tap / 3) * 66 + (tap % 3);
        const uint32_t ah_base = sxh_u + (uint32_t)(shift + wm * 64 + rowA) * 80 + colh;
        const uint32_t al_base = sxl_u + (uint32_t)(shift + wm * 64 + rowA) * 80 + colh;
        for (int chunk = 0; chunk < 2; ++chunk) {
            const uint2* ph = g_WxF + (size_t)(tap * 4 + chunk) * 1024 + wn * 128 + lane;
            const uint2* pl = ph + 2048;
            uint2 bh[4], bl[4];
#pragma unroll
            for (int nt = 0; nt < 4; ++nt) { bh[nt] = ph[nt * 32]; bl[nt] = pl[nt * 32]; }
#pragma unroll
            for (int mt = 0; mt < 4; ++mt) {
                uint32_t ah[4], al[4];
                LDMX4(ah, ah_base + mt * (16 * 80) + chunk * 32);
                LDMX4(al, al_base + mt * (16 * 80) + chunk * 32);
#pragma unroll
                for (int nt = 0; nt < 4; ++nt) {
                    MMA_BF16(acc[mt][nt], ah, bh[nt]);
                    MMA_BF16(acc[mt][nt], al, bh[nt]);
                    MMA_BF16(acc[mt][nt], ah, bl[nt]);
                }
            }
        }
    }

    __syncthreads();   // done reading slabs; z aliases them

    // ---- scatter z to smem ----
#pragma unroll
    for (int mt = 0; mt < 4; ++mt)
#pragma unroll
        for (int nt = 0; nt < 4; ++nt) {
            int px = wm * 64 + mt * 16 + (lane >> 2);
            int n  = wn * 32 + nt * 8 + (lane & 3) * 2;
            *(float2*)(zs + px * 260 + n)       = make_float2(acc[mt][nt][0], acc[mt][nt][1]);
            *(float2*)(zs + (px + 8) * 260 + n) = make_float2(acc[mt][nt][2], acc[mt][nt][3]);
        }
    __syncthreads();

    // ---- epilogue: gates, c/h update, residual add ----
    const int pxl = tid >> 2;
    const int q   = q0 + pxl;
    const int py  = q / 66, pxc = q % 66;
    const bool inter = (q < PPX) && py >= 1 && py <= 64 && pxc >= 1 && pxc <= 64;
    if (inter) {
        float* cpt = g_c + ((size_t)b * PPX + q) * 64;
        unsigned short* hoh = (unsigned short*)(g_h_hi[(t + 1) & 1] + GRD * 64 + ((size_t)b * PPX + q) * 64);
        unsigned short* hol = (unsigned short*)(g_h_lo[(t + 1) & 1] + GRD * 64 + ((size_t)b * PPX + q) * 64);
        float* op = out + ((size_t)bt * 4096 + (py - 1) * 64 + (pxc - 1)) * 64;
        const float* zrow = zs + pxl * 260;
        const int f0base = (tid & 3) * 16;
#pragma unroll
        for (int j4 = 0; j4 < 4; ++j4) {
            int f0 = f0base + j4 * 4;
            float4 zi = *(const float4*)(zrow + f0);
            float4 zf = *(const float4*)(zrow + 64 + f0);
            float4 zc = *(const float4*)(zrow + 128 + f0);
            float4 zo = *(const float4*)(zrow + 192 + f0);
            float4 c4 = *(float4*)(cpt + f0);
            float4 o4 = *(float4*)(op + f0);
            unsigned short hh[4], hl[4];
#pragma unroll
            for (int e = 0; e < 4; ++e) {
                int f = f0 + e;
                float vi = (&zi.x)[e] + bs[f];
                float vf = (&zf.x)[e] + bs[64 + f];
                float vc = (&zc.x)[e] + bs[128 + f];
                float vo = (&zo.x)[e] + bs[192 + f];
                float ig = __saturatef(fmaf(0.2f, vi, 0.5f));
                float fg = __saturatef(fmaf(0.2f, vf, 0.5f));
                float og = __saturatef(fmaf(0.2f, vo, 0.5f));
                float cn = fmaf(fg, (&c4.x)[e], ig * tanhf(vc));
                (&c4.x)[e] = cn;
                float hv = og * tanhf(cn);
                (&o4.x)[e] += hv;
                __nv_bfloat16 hb = __float2bfloat16(hv);
                hh[e] = __bfloat16_as_ushort(hb);
                hl[e] = __bfloat16_as_ushort(__float2bfloat16(hv - __bfloat162float(hb)));
            }
            *(float4*)(cpt + f0) = c4;
            *(float4*)(op + f0)  = o4;
            uint2 phv = make_uint2((uint32_t)hh[0] | ((uint32_t)hh[1] << 16),
                                   (uint32_t)hh[2] | ((uint32_t)hh[3] << 16));
            uint2 plv = make_uint2((uint32_t)hl[0] | ((uint32_t)hl[1] << 16),
                                   (uint32_t)hl[2] | ((uint32_t)hl[3] << 16));
            *(uint2*)(hoh + f0) = phv;
            *(uint2*)(hol + f0) = plv;
        }
    }
}

// ---------------------------------------------------------------------------
extern "C" void kernel_launch(void* const* d_in, const int* in_sizes, int n_in,
                              void* d_out, int out_size)
{
    const float* x  = (const float*)d_in[0];
    const float* Wx = (const float*)d_in[1];
    const float* Wh = (const float*)d_in[2];
    const float* b  = (const float*)d_in[3];
    const float* Wp = (const float*)d_in[4];
    const float* bp = (const float*)d_in[5];
    float* out = (float*)d_out;

    cudaFuncSetAttribute(step_kernel,
                         cudaFuncAttributeMaxDynamicSharedMemorySize, SM_TOTAL);

    zero_kernel<<<(NTOT + 255) / 256, 256>>>();
    pad_x_kernel<<<(int)((XTOT + 255) / 256), 256>>>(x);
    prep_w_kernel<<<(73728 + 36864 + 255) / 256, 256>>>(Wx, Wh);
    residual_kernel<<<(BBATCH * TT * 4096 * 64) / 256, 256>>>(x, Wp, bp, out);

    dim3 grid(35, BBATCH);
    for (int t = 0; t < TT; ++t)
        step_kernel<<<grid, 512, SM_TOTAL>>>(b, out, t);
}

// round 8
// speedup vs baseline: 4.3153x; 1.2869x over previous
#include <cuda_runtime.h>
#include <cuda_fp16.h>
#include <cstdint>
#include <math.h>

#define BBATCH 4
#define TT   16
#define PPX  4356          // 66*66 padded pixels
#define GRD  192           // guard pixels at both ends of padded arrays
#define NTOT ((2*GRD + BBATCH*PPX) * 64)
#define XTOT ((2*GRD + BBATCH*TT*PPX) * 32)
#define NC   (BBATCH * PPX * 64)

// ---------------- static device state ----------------
__device__ __half g_h_hi[2][NTOT];
__device__ __half g_h_lo[2][NTOT];
__device__ float  g_c[NC];
__device__ __half g_x_hi[XTOT];
__device__ __half g_x_lo[XTOT];
// mma.sync B fragments (single fp16 plane), lane-ordered:
// Wh: [tap(9)][chunk(4)][ntile(32)][lane(32)] -> uint2 {b0,b1}
// Wx: [tap(9)][chunk(2)][ntile(32)][lane(32)]
__device__ uint2 g_WhF[9 * 4 * 32 * 32];
__device__ uint2 g_WxF[9 * 2 * 32 * 32];

// ---------------- helpers ----------------
__device__ __forceinline__ uint32_t smem_u32(const void* p) {
    uint32_t a;
    asm("{ .reg .u64 t; cvta.to.shared.u64 t, %1; cvt.u32.u64 %0, t; }" : "=r"(a) : "l"(p));
    return a;
}

#define LDMX4(r, addr) \
    asm volatile("ldmatrix.sync.aligned.m8n8.x4.shared.b16 {%0,%1,%2,%3}, [%4];" \
        : "=r"((r)[0]), "=r"((r)[1]), "=r"((r)[2]), "=r"((r)[3]) : "r"(addr))

#define MMA_FP16(d, a, bf) \
    asm volatile("mma.sync.aligned.m16n8k16.row.col.f32.f16.f16.f32 " \
        "{%0,%1,%2,%3}, {%4,%5,%6,%7}, {%8,%9}, {%0,%1,%2,%3};" \
        : "+f"((d)[0]), "+f"((d)[1]), "+f"((d)[2]), "+f"((d)[3]) \
        : "r"((a)[0]), "r"((a)[1]), "r"((a)[2]), "r"((a)[3]), "r"((bf).x), "r"((bf).y))

__device__ __forceinline__ uint32_t enc_h(float v) {
    return (uint32_t)__half_as_ushort(__float2half_rn(v));
}

// ---------------- prep kernels ----------------
__global__ void zero_kernel() {
    int i = blockIdx.x * blockDim.x + threadIdx.x;
    if (i < NTOT) {
        g_h_hi[0][i] = __float2half(0.f); g_h_hi[1][i] = __float2half(0.f);
        g_h_lo[0][i] = __float2half(0.f); g_h_lo[1][i] = __float2half(0.f);
    }
    if (i < NC) g_c[i] = 0.f;
}

__global__ void pad_x_kernel(const float* __restrict__ x) {
    long i = (long)blockIdx.x * blockDim.x + threadIdx.x;
    if (i >= XTOT) return;
    int ci = (int)(i & 31);
    long p = i >> 5;
    float v = 0.f;
    if (p >= GRD && p < GRD + (long)BBATCH * TT * PPX) {
        long pp = p - GRD;
        int bt = (int)(pp / PPX), q = (int)(pp % PPX);
        int py = q / 66, px = q % 66;
        if (py >= 1 && py <= 64 && px >= 1 && px <= 64)
            v = x[(((long)bt * 4096) + (py - 1) * 64 + (px - 1)) * 32 + ci];
    }
    __half h = __float2half_rn(v);
    g_x_hi[i] = h;
    g_x_lo[i] = __float2half_rn(v - __half2float(h));
}

__global__ void prep_w_kernel(const float* __restrict__ Wx, const float* __restrict__ Wh) {
    int idx = blockIdx.x * blockDim.x + threadIdx.x;
    if (idx < 36864) {                    // Wh fragments: tap(9) x chunk(4)
        int tap   = idx >> 12;
        int r     = idx & 4095;
        int chunk = r >> 10;
        int r3    = r & 1023;
        int nt    = r3 >> 5, lane = r3 & 31;
        int k0 = chunk * 16 + (lane & 3) * 2;
        int n  = nt * 8 + (lane >> 2);
        float v00 = Wh[((size_t)tap * 64 + k0    ) * 256 + n];
        float v01 = Wh[((size_t)tap * 64 + k0 + 1) * 256 + n];
        float v10 = Wh[((size_t)tap * 64 + k0 + 8) * 256 + n];
        float v11 = Wh[((size_t)tap * 64 + k0 + 9) * 256 + n];
        uint2 o;
        o.x = enc_h(v00) | (enc_h(v01) << 16);
        o.y = enc_h(v10) | (enc_h(v11) << 16);
        g_WhF[idx] = o;
    } else if (idx < 36864 + 18432) {     // Wx fragments: tap(9) x chunk(2)
        int j     = idx - 36864;
        int tap   = j >> 11;
        int r     = j & 2047;
        int chunk = r >> 10;
        int r3    = r & 1023;
        int nt    = r3 >> 5, lane = r3 & 31;
        int k0 = chunk * 16 + (lane & 3) * 2;
        int n  = nt * 8 + (lane >> 2);
        float v00 = Wx[((size_t)tap * 32 + k0    ) * 256 + n];
        float v01 = Wx[((size_t)tap * 32 + k0 + 1) * 256 + n];
        float v10 = Wx[((size_t)tap * 32 + k0 + 8) * 256 + n];
        float v11 = Wx[((size_t)tap * 32 + k0 + 9) * 256 + n];
        uint2 o;
        o.x = enc_h(v00) | (enc_h(v01) << 16);
        o.y = enc_h(v10) | (enc_h(v11) << 16);
        g_WxF[j] = o;
    }
}

// ---------------- fused ConvLSTM step (mma.sync fp16, A split 2-product) ----
// smem layout (bytes):
//   phase 1 (conv):   [0      : 37728) h_hi slab  262 rows x 144B
//                     [37728  : 75456) h_lo slab
//                     [75456  : 96416) x_hi slab  262 rows x 80B
//                     [96416  :117376) x_lo slab
//   phase 2 (epilog): [0      :133120) z[128][260] fp32  (aliases slabs)
//   always:           [133120 :134144) bias[256] fp32
//                     [134144 :142336) Wp[32][64] fp32
//                     [142336 :142592) bp[64] fp32
#define SM_SHH   0
#define SM_SHL   37728
#define SM_SXH   75456
#define SM_SXL   96416
#define SM_BIAS  133120
#define SM_WP    134144
#define SM_BP    142336
#define SM_TOTAL 142592

__global__ void __launch_bounds__(512, 1)
step_kernel(const float* __restrict__ bias, const float* __restrict__ Wp,
            const float* __restrict__ bp, const float* __restrict__ xin,
            float* __restrict__ out, int t)
{
    extern __shared__ __align__(16) char smem[];
    float* zs   = (float*)smem;
    float* bs   = (float*)(smem + SM_BIAS);
    float* wp_s = (float*)(smem + SM_WP);
    float* bp_s = (float*)(smem + SM_BP);

    const int tid  = threadIdx.x;
    const int lane = tid & 31;
    const int wid  = tid >> 5;      // 0..15
    const int wm   = wid & 1;       // M half (64 rows)
    const int wn   = wid >> 1;      // 0..7, N group of 32
    const int b    = blockIdx.y;
    const int q0   = blockIdx.x * 128;
    const int bt   = b * TT + t;

    if (tid < 256) bs[tid] = bias[tid];
    for (int i = tid; i < 2048; i += 512) wp_s[i] = Wp[i];
    if (tid < 64) bp_s[tid] = bp[tid];

    // ---- load slabs (padded rows q0-67 .. q0+194) ----
    {
        long off = (long)GRD * 64 + ((long)b * PPX + q0 - 67) * 64;
        const uint4* sh = (const uint4*)(g_h_hi[t & 1] + off);
        const uint4* sl = (const uint4*)(g_h_lo[t & 1] + off);
        for (int i = tid; i < 2096; i += 512) {
            int r = i >> 3, c = i & 7;
            *(uint4*)(smem + SM_SHH + r * 144 + c * 16) = sh[i];
            *(uint4*)(smem + SM_SHL + r * 144 + c * 16) = sl[i];
        }
        long offx = (long)GRD * 32 + ((long)bt * PPX + q0 - 67) * 32;
        const uint4* xh = (const uint4*)(g_x_hi + offx);
        const uint4* xl = (const uint4*)(g_x_lo + offx);
        for (int i = tid; i < 1048; i += 512) {
            int r = i >> 2, c = i & 3;
            *(uint4*)(smem + SM_SXH + r * 80 + c * 16) = xh[i];
            *(uint4*)(smem + SM_SXL + r * 80 + c * 16) = xl[i];
        }
    }
    __syncthreads();

    float acc[4][4][4];
#pragma unroll
    for (int mt = 0; mt < 4; ++mt)
#pragma unroll
        for (int nt = 0; nt < 4; ++nt)
#pragma unroll
            for (int e = 0; e < 4; ++e) acc[mt][nt][e] = 0.f;

    const uint32_t shh_u = smem_u32(smem + SM_SHH);
    const uint32_t shl_u = smem_u32(smem + SM_SHL);
    const uint32_t sxh_u = smem_u32(smem + SM_SXH);
    const uint32_t sxl_u = smem_u32(smem + SM_SXL);
    const int rowA = lane & 15;
    const int colh = (lane >> 4) * 16;

    // ---- h taps: 9 x (K=64, 4 k16-chunks) x 2 products (A hi/lo) ----
    for (int tap = 0; tap < 9; ++tap) {
        const int shift = (tap / 3) * 66 + (tap % 3);
        const uint32_t ah_base = shh_u + (uint32_t)(shift + wm * 64 + rowA) * 144 + colh;
        const uint32_t al_base = shl_u + (uint32_t)(shift + wm * 64 + rowA) * 144 + colh;
        for (int chunk = 0; chunk < 4; ++chunk) {
            const uint2* ph = g_WhF + (size_t)(tap * 4 + chunk) * 1024 + wn * 128 + lane;
            uint2 bh[4];
#pragma unroll
            for (int nt = 0; nt < 4; ++nt) bh[nt] = ph[nt * 32];
#pragma unroll
            for (int mt = 0; mt < 4; ++mt) {
                uint32_t ah[4], al[4];
                LDMX4(ah, ah_base + mt * (16 * 144) + chunk * 32);
                LDMX4(al, al_base + mt * (16 * 144) + chunk * 32);
#pragma unroll
                for (int nt = 0; nt < 4; ++nt) {
                    MMA_FP16(acc[mt][nt], ah, bh[nt]);
                    MMA_FP16(acc[mt][nt], al, bh[nt]);
                }
            }
        }
    }

    // ---- x taps: 9 x (K=32, 2 k16-chunks) x 2 products ----
    for (int tap = 0; tap < 9; ++tap) {
        const int shift = (tap / 3) * 66 + (tap % 3);
        const uint32_t ah_base = sxh_u + (uint32_t)(shift + wm * 64 + rowA) * 80 + colh;
        const uint32_t al_base = sxl_u + (uint32_t)(shift + wm * 64 + rowA) * 80 + colh;
        for (int chunk = 0; chunk < 2; ++chunk) {
            const uint2* ph = g_WxF + (size_t)(tap * 2 + chunk) * 1024 + wn * 128 + lane;
            uint2 bh[4];
#pragma unroll
            for (int nt = 0; nt < 4; ++nt) bh[nt] = ph[nt * 32];
#pragma unroll
            for (int mt = 0; mt < 4; ++mt) {
                uint32_t ah[4], al[4];
                LDMX4(ah, ah_base + mt * (16 * 80) + chunk * 32);
                LDMX4(al, al_base + mt * (16 * 80) + chunk * 32);
#pragma unroll
                for (int nt = 0; nt < 4; ++nt) {
                    MMA_FP16(acc[mt][nt], ah, bh[nt]);
                    MMA_FP16(acc[mt][nt], al, bh[nt]);
                }
            }
        }
    }

    __syncthreads();   // done reading slabs; z aliases them

    // ---- scatter z to smem ----
#pragma unroll
    for (int mt = 0; mt < 4; ++mt)
#pragma unroll
        for (int nt = 0; nt < 4; ++nt) {
            int px = wm * 64 + mt * 16 + (lane >> 2);
            int n  = wn * 32 + nt * 8 + (lane & 3) * 2;
            *(float2*)(zs + px * 260 + n)       = make_float2(acc[mt][nt][0], acc[mt][nt][1]);
            *(float2*)(zs + (px + 8) * 260 + n) = make_float2(acc[mt][nt][2], acc[mt][nt][3]);
        }
    __syncthreads();

    // ---- epilogue: gates, c/h update, fused 1x1 residual ----
    const int pxl = tid >> 2;
    const int q   = q0 + pxl;
    const int py  = q / 66, pxc = q % 66;
    const bool inter = (q < PPX) && py >= 1 && py <= 64 && pxc >= 1 && pxc <= 64;
    if (inter) {
        float* cpt = g_c + ((size_t)b * PPX + q) * 64;
        unsigned short* hoh = (unsigned short*)(g_h_hi[(t + 1) & 1] + GRD * 64 + ((size_t)b * PPX + q) * 64);
        unsigned short* hol = (unsigned short*)(g_h_lo[(t + 1) & 1] + GRD * 64 + ((size_t)b * PPX + q) * 64);
        float* op = out + ((size_t)bt * 4096 + (py - 1) * 64 + (pxc - 1)) * 64;
        const float* zrow = zs + pxl * 260;
        const float* xrow = xin + ((size_t)bt * 4096 + (py - 1) * 64 + (pxc - 1)) * 32;
        const int f0base = (tid & 3) * 16;

        // x pixel row into registers (8 x float4)
        float4 xr[8];
#pragma unroll
        for (int i = 0; i < 8; ++i) xr[i] = __ldg((const float4*)xrow + i);

#pragma unroll
        for (int j4 = 0; j4 < 4; ++j4) {
            int f0 = f0base + j4 * 4;
            // residual: res = bp + x . Wp[:, f0:f0+4]
            float4 res = *(const float4*)(bp_s + f0);
#pragma unroll
            for (int ci4 = 0; ci4 < 8; ++ci4) {
                const float* xv = &xr[ci4].x;
#pragma unroll
                for (int cc = 0; cc < 4; ++cc) {
                    float4 w = *(const float4*)(wp_s + (ci4 * 4 + cc) * 64 + f0);
                    float xs = xv[cc];
                    res.x = fmaf(xs, w.x, res.x);
                    res.y = fmaf(xs, w.y, res.y);
                    res.z = fmaf(xs, w.z, res.z);
                    res.w = fmaf(xs, w.w, res.w);
                }
            }

            float4 zi = *(const float4*)(zrow + f0);
            float4 zf = *(const float4*)(zrow + 64 + f0);
            float4 zc = *(const float4*)(zrow + 128 + f0);
            float4 zo = *(const float4*)(zrow + 192 + f0);
            float4 c4 = *(float4*)(cpt + f0);
            float4 o4;
            unsigned short hh[4], hl[4];
#pragma unroll
            for (int e = 0; e < 4; ++e) {
                int f = f0 + e;
                float vi = (&zi.x)[e] + bs[f];
                float vf = (&zf.x)[e] + bs[64 + f];
                float vc = (&zc.x)[e] + bs[128 + f];
                float vo = (&zo.x)[e] + bs[192 + f];
                float ig = __saturatef(fmaf(0.2f, vi, 0.5f));
                float fg = __saturatef(fmaf(0.2f, vf, 0.5f));
                float og = __saturatef(fmaf(0.2f, vo, 0.5f));
                float cn = fmaf(fg, (&c4.x)[e], ig * tanhf(vc));
                (&c4.x)[e] = cn;
                float hv = og * tanhf(cn);
                (&o4.x)[e] = hv + (&res.x)[e];
                __half hb = __float2half_rn(hv);
                hh[e] = __half_as_ushort(hb);
                hl[e] = __half_as_ushort(__float2half_rn(hv - __half2float(hb)));
            }
            *(float4*)(cpt + f0) = c4;
            *(float4*)(op + f0)  = o4;
            uint2 phv = make_uint2((uint32_t)hh[0] | ((uint32_t)hh[1] << 16),
                                   (uint32_t)hh[2] | ((uint32_t)hh[3] << 16));
            uint2 plv = make_uint2((uint32_t)hl[0] | ((uint32_t)hl[1] << 16),
                                   (uint32_t)hl[2] | ((uint32_t)hl[3] << 16));
            *(uint2*)(hoh + f0) = phv;
            *(uint2*)(hol + f0) = plv;
        }
    }
}

// ---------------------------------------------------------------------------
extern "C" void kernel_launch(void* const* d_in, const int* in_sizes, int n_in,
                              void* d_out, int out_size)
{
    const float* x  = (const float*)d_in[0];
    const float* Wx = (const float*)d_in[1];
    const float* Wh = (const float*)d_in[2];
    const float* b  = (const float*)d_in[3];
    const float* Wp = (const float*)d_in[4];
    const float* bp = (const float*)d_in[5];
    float* out = (float*)d_out;

    cudaFuncSetAttribute(step_kernel,
                         cudaFuncAttributeMaxDynamicSharedMemorySize, SM_TOTAL);

    zero_kernel<<<(NTOT + 255) / 256, 256>>>();
    pad_x_kernel<<<(int)((XTOT + 255) / 256), 256>>>(x);
    prep_w_kernel<<<(36864 + 18432 + 255) / 256, 256>>>(Wx, Wh);

    dim3 grid(35, BBATCH);
    for (int t = 0; t < TT; ++t)
        step_kernel<<<grid, 512, SM_TOTAL>>>(b, Wp, bp, x, out, t);
}

// round 9
// speedup vs baseline: 4.9562x; 1.1485x over previous
#include <cuda_runtime.h>
#include <cuda_fp16.h>
#include <cstdint>
#include <math.h>

#define BBATCH 4
#define TT   16
#define PPX  4356          // 66*66 padded pixels
#define GRD  192           // guard pixels at both ends of padded arrays
#define NTOT ((2*GRD + BBATCH*PPX) * 64)
#define XTOT ((2*GRD + BBATCH*TT*PPX) * 32)
#define NC   (BBATCH * PPX * 64)
#define NSTRIP 35
#define ZXN  (BBATCH * TT * NSTRIP * 128 * 256)   // 73,400,320 floats

// ---------------- static device state ----------------
__device__ __half g_h[2][NTOT];          // hidden state, single fp16 plane
__device__ float  g_c[NC];
__device__ __half g_x[XTOT];             // padded input, single fp16 plane
__device__ float  g_zx[ZXN];             // precomputed x-conv (no bias)
// mma.sync B fragments (single fp16 plane), lane-ordered:
// Wh: [tap(9)][chunk(4)][ntile(32)][lane(32)] -> uint2 {b0,b1}
// Wx: [tap(9)][chunk(2)][ntile(32)][lane(32)]
__device__ uint2 g_WhF[9 * 4 * 32 * 32];
__device__ uint2 g_WxF[9 * 2 * 32 * 32];

// ---------------- helpers ----------------
__device__ __forceinline__ uint32_t smem_u32(const void* p) {
    uint32_t a;
    asm("{ .reg .u64 t; cvta.to.shared.u64 t, %1; cvt.u32.u64 %0, t; }" : "=r"(a) : "l"(p));
    return a;
}

#define LDMX4(r, addr) \
    asm volatile("ldmatrix.sync.aligned.m8n8.x4.shared.b16 {%0,%1,%2,%3}, [%4];" \
        : "=r"((r)[0]), "=r"((r)[1]), "=r"((r)[2]), "=r"((r)[3]) : "r"(addr))

#define MMA_FP16(d, a, bf) \
    asm volatile("mma.sync.aligned.m16n8k16.row.col.f32.f16.f16.f32 " \
        "{%0,%1,%2,%3}, {%4,%5,%6,%7}, {%8,%9}, {%0,%1,%2,%3};" \
        : "+f"((d)[0]), "+f"((d)[1]), "+f"((d)[2]), "+f"((d)[3]) \
        : "r"((a)[0]), "r"((a)[1]), "r"((a)[2]), "r"((a)[3]), "r"((bf).x), "r"((bf).y))

__device__ __forceinline__ uint32_t enc_h(float v) {
    return (uint32_t)__half_as_ushort(__float2half_rn(v));
}

// ---------------- prep kernels ----------------
__global__ void zero_kernel() {
    int i = blockIdx.x * blockDim.x + threadIdx.x;
    if (i < NTOT) { g_h[0][i] = __float2half(0.f); g_h[1][i] = __float2half(0.f); }
    if (i < NC) g_c[i] = 0.f;
}

__global__ void pad_x_kernel(const float* __restrict__ x) {
    long i = (long)blockIdx.x * blockDim.x + threadIdx.x;
    if (i >= XTOT) return;
    int ci = (int)(i & 31);
    long p = i >> 5;
    float v = 0.f;
    if (p >= GRD && p < GRD + (long)BBATCH * TT * PPX) {
        long pp = p - GRD;
        int bt = (int)(pp / PPX), q = (int)(pp % PPX);
        int py = q / 66, px = q % 66;
        if (py >= 1 && py <= 64 && px >= 1 && px <= 64)
            v = x[(((long)bt * 4096) + (py - 1) * 64 + (px - 1)) * 32 + ci];
    }
    g_x[i] = __float2half_rn(v);
}

__global__ void prep_w_kernel(const float* __restrict__ Wx, const float* __restrict__ Wh) {
    int idx = blockIdx.x * blockDim.x + threadIdx.x;
    if (idx < 36864) {                    // Wh fragments: tap(9) x chunk(4)
        int tap   = idx >> 12;
        int r     = idx & 4095;
        int chunk = r >> 10;
        int r3    = r & 1023;
        int nt    = r3 >> 5, lane = r3 & 31;
        int k0 = chunk * 16 + (lane & 3) * 2;
        int n  = nt * 8 + (lane >> 2);
        float v00 = Wh[((size_t)tap * 64 + k0    ) * 256 + n];
        float v01 = Wh[((size_t)tap * 64 + k0 + 1) * 256 + n];
        float v10 = Wh[((size_t)tap * 64 + k0 + 8) * 256 + n];
        float v11 = Wh[((size_t)tap * 64 + k0 + 9) * 256 + n];
        uint2 o;
        o.x = enc_h(v00) | (enc_h(v01) << 16);
        o.y = enc_h(v10) | (enc_h(v11) << 16);
        g_WhF[idx] = o;
    } else if (idx < 36864 + 18432) {     // Wx fragments: tap(9) x chunk(2)
        int j     = idx - 36864;
        int tap   = j >> 11;
        int r     = j & 2047;
        int chunk = r >> 10;
        int r3    = r & 1023;
        int nt    = r3 >> 5, lane = r3 & 31;
        int k0 = chunk * 16 + (lane & 3) * 2;
        int n  = nt * 8 + (lane >> 2);
        float v00 = Wx[((size_t)tap * 32 + k0    ) * 256 + n];
        float v01 = Wx[((size_t)tap * 32 + k0 + 1) * 256 + n];
        float v10 = Wx[((size_t)tap * 32 + k0 + 8) * 256 + n];
        float v11 = Wx[((size_t)tap * 32 + k0 + 9) * 256 + n];
        uint2 o;
        o.x = enc_h(v00) | (enc_h(v01) << 16);
        o.y = enc_h(v10) | (enc_h(v11) << 16);
        g_WxF[j] = o;
    }
}

// ---------------- xconv: zx = conv3x3(x, Wx) for all frames (parallel) ------
// smem: phase 1: x slab 262 rows x 80B = 20960; phase 2: z[128][260] fp32 (alias)
#define XC_SMEM 133120

__global__ void __launch_bounds__(512, 1)
xconv_kernel()
{
    extern __shared__ __align__(16) char smem[];
    float* zs = (float*)smem;

    const int tid  = threadIdx.x;
    const int lane = tid & 31;
    const int wid  = tid >> 5;
    const int wm   = wid & 1;
    const int wn   = wid >> 1;
    const int bt   = blockIdx.y;
    const int q0   = blockIdx.x * 128;

    // ---- load x slab (padded rows q0-67 .. q0+194) ----
    {
        long offx = (long)GRD * 32 + ((long)bt * PPX + q0 - 67) * 32;
        const uint4* xh = (const uint4*)(g_x + offx);
        for (int i = tid; i < 1048; i += 512) {
            int r = i >> 2, c = i & 3;
            *(uint4*)(smem + r * 80 + c * 16) = xh[i];
        }
    }
    __syncthreads();

    float acc[4][4][4];
#pragma unroll
    for (int mt = 0; mt < 4; ++mt)
#pragma unroll
        for (int nt = 0; nt < 4; ++nt)
#pragma unroll
            for (int e = 0; e < 4; ++e) acc[mt][nt][e] = 0.f;

    const uint32_t sx_u = smem_u32(smem);
    const int rowA = lane & 15;
    const int colh = (lane >> 4) * 16;

    for (int tap = 0; tap < 9; ++tap) {
        const int shift = (tap / 3) * 66 + (tap % 3);
        const uint32_t a_base = sx_u + (uint32_t)(shift + wm * 64 + rowA) * 80 + colh;
#pragma unroll
        for (int chunk = 0; chunk < 2; ++chunk) {
            const uint2* ph = g_WxF + (size_t)(tap * 2 + chunk) * 1024 + wn * 128 + lane;
            uint2 bh[4];
#pragma unroll
            for (int nt = 0; nt < 4; ++nt) bh[nt] = ph[nt * 32];
#pragma unroll
            for (int mt = 0; mt < 4; ++mt) {
                uint32_t ah[4];
                LDMX4(ah, a_base + mt * (16 * 80) + chunk * 32);
#pragma unroll
                for (int nt = 0; nt < 4; ++nt) MMA_FP16(acc[mt][nt], ah, bh[nt]);
            }
        }
    }

    __syncthreads();   // done reading slab; z aliases it

#pragma unroll
    for (int mt = 0; mt < 4; ++mt)
#pragma unroll
        for (int nt = 0; nt < 4; ++nt) {
            int px = wm * 64 + mt * 16 + (lane >> 2);
            int n  = wn * 32 + nt * 8 + (lane & 3) * 2;
            *(float2*)(zs + px * 260 + n)       = make_float2(acc[mt][nt][0], acc[mt][nt][1]);
            *(float2*)(zs + (px + 8) * 260 + n) = make_float2(acc[mt][nt][2], acc[mt][nt][3]);
        }
    __syncthreads();

    // ---- coalesced store to gmem ----
    float* dst = g_zx + ((size_t)bt * NSTRIP + blockIdx.x) * 128 * 256;
    for (int i = tid; i < 128 * 256; i += 512) {
        int row = i >> 8, col = i & 255;
        dst[i] = zs[row * 260 + col];
    }
}

// ---------------- fused ConvLSTM step (h-conv only, mma.sync fp16) ----------
// smem layout (bytes):
//   phase 1 (conv):   [0      : 37728) h slab  262 rows x 144B
//   phase 2 (epilog): [0      :133120) z[128][260] fp32  (aliases slab)
//   always:           [133120 :134144) bias[256] fp32
//                     [134144 :142336) Wp[32][64] fp32
//                     [142336 :142592) bp[64] fp32
#define SM_BIAS  133120
#define SM_WP    134144
#define SM_BP    142336
#define SM_TOTAL 142592

__global__ void __launch_bounds__(512, 1)
step_kernel(const float* __restrict__ bias, const float* __restrict__ Wp,
            const float* __restrict__ bp, const float* __restrict__ xin,
            float* __restrict__ out, int t)
{
    extern __shared__ __align__(16) char smem[];
    float* zs   = (float*)smem;
    float* bs   = (float*)(smem + SM_BIAS);
    float* wp_s = (float*)(smem + SM_WP);
    float* bp_s = (float*)(smem + SM_BP);

    const int tid  = threadIdx.x;
    const int lane = tid & 31;
    const int wid  = tid >> 5;
    const int wm   = wid & 1;
    const int wn   = wid >> 1;
    const int b    = blockIdx.y;
    const int q0   = blockIdx.x * 128;
    const int bt   = b * TT + t;

    if (tid < 256) bs[tid] = bias[tid];
    for (int i = tid; i < 2048; i += 512) wp_s[i] = Wp[i];
    if (tid < 64) bp_s[tid] = bp[tid];

    // ---- load h slab (padded rows q0-67 .. q0+194) ----
    {
        long off = (long)GRD * 64 + ((long)b * PPX + q0 - 67) * 64;
        const uint4* sh = (const uint4*)(g_h[t & 1] + off);
        for (int i = tid; i < 2096; i += 512) {
            int r = i >> 3, c = i & 7;
            *(uint4*)(smem + r * 144 + c * 16) = sh[i];
        }
    }
    __syncthreads();

    float acc[4][4][4];
#pragma unroll
    for (int mt = 0; mt < 4; ++mt)
#pragma unroll
        for (int nt = 0; nt < 4; ++nt)
#pragma unroll
            for (int e = 0; e < 4; ++e) acc[mt][nt][e] = 0.f;

    const uint32_t sh_u = smem_u32(smem);
    const int rowA = lane & 15;
    const int colh = (lane >> 4) * 16;

    // ---- h taps: 9 x (K=64, 4 k16-chunks), single fp16 product ----
    for (int tap = 0; tap < 9; ++tap) {
        const int shift = (tap / 3) * 66 + (tap % 3);
        const uint32_t a_base = sh_u + (uint32_t)(shift + wm * 64 + rowA) * 144 + colh;
#pragma unroll
        for (int chunk = 0; chunk < 4; ++chunk) {
            const uint2* ph = g_WhF + (size_t)(tap * 4 + chunk) * 1024 + wn * 128 + lane;
            uint2 bh[4];
#pragma unroll
            for (int nt = 0; nt < 4; ++nt) bh[nt] = ph[nt * 32];
#pragma unroll
            for (int mt = 0; mt < 4; ++mt) {
                uint32_t ah[4];
                LDMX4(ah, a_base + mt * (16 * 144) + chunk * 32);
#pragma unroll
                for (int nt = 0; nt < 4; ++nt) MMA_FP16(acc[mt][nt], ah, bh[nt]);
            }
        }
    }

    __syncthreads();   // done reading slab; z aliases it

    // ---- scatter z to smem ----
#pragma unroll
    for (int mt = 0; mt < 4; ++mt)
#pragma unroll
        for (int nt = 0; nt < 4; ++nt) {
            int px = wm * 64 + mt * 16 + (lane >> 2);
            int n  = wn * 32 + nt * 8 + (lane & 3) * 2;
            *(float2*)(zs + px * 260 + n)       = make_float2(acc[mt][nt][0], acc[mt][nt][1]);
            *(float2*)(zs + (px + 8) * 260 + n) = make_float2(acc[mt][nt][2], acc[mt][nt][3]);
        }
    __syncthreads();

    // ---- epilogue: zx + bias + gates, c/h update, fused 1x1 residual ----
    const int pxl = tid >> 2;
    const int q   = q0 + pxl;
    const int py  = q / 66, pxc = q % 66;
    const bool inter = (q < PPX) && py >= 1 && py <= 64 && pxc >= 1 && pxc <= 64;
    if (inter) {
        float* cpt = g_c + ((size_t)b * PPX + q) * 64;
        unsigned short* ho = (unsigned short*)(g_h[(t + 1) & 1] + GRD * 64 + ((size_t)b * PPX + q) * 64);
        float* op = out + ((size_t)bt * 4096 + (py - 1) * 64 + (pxc - 1)) * 64;
        const float* zrow  = zs + pxl * 260;
        const float* zxrow = g_zx + (((size_t)bt * NSTRIP + blockIdx.x) * 128 + pxl) * 256;
        const float* xrow  = xin + ((size_t)bt * 4096 + (py - 1) * 64 + (pxc - 1)) * 32;
        const int f0base = (tid & 3) * 16;

        float4 xr[8];
#pragma unroll
        for (int i = 0; i < 8; ++i) xr[i] = __ldg((const float4*)xrow + i);

#pragma unroll
        for (int j4 = 0; j4 < 4; ++j4) {
            int f0 = f0base + j4 * 4;
            // residual: res = bp + x . Wp[:, f0:f0+4]
            float4 res = *(const float4*)(bp_s + f0);
#pragma unroll
            for (int ci4 = 0; ci4 < 8; ++ci4) {
                const float* xv = &xr[ci4].x;
#pragma unroll
                for (int cc = 0; cc < 4; ++cc) {
                    float4 w = *(const float4*)(wp_s + (ci4 * 4 + cc) * 64 + f0);
                    float xs = xv[cc];
                    res.x = fmaf(xs, w.x, res.x);
                    res.y = fmaf(xs, w.y, res.y);
                    res.z = fmaf(xs, w.z, res.z);
                    res.w = fmaf(xs, w.w, res.w);
                }
            }

            float4 zi = *(const float4*)(zrow + f0);
            float4 zf = *(const float4*)(zrow + 64 + f0);
            float4 zc = *(const float4*)(zrow + 128 + f0);
            float4 zo = *(const float4*)(zrow + 192 + f0);
            float4 xi = __ldg((const float4*)(zxrow + f0));
            float4 xf = __ldg((const float4*)(zxrow + 64 + f0));
            float4 xc = __ldg((const float4*)(zxrow + 128 + f0));
            float4 xo = __ldg((const float4*)(zxrow + 192 + f0));
            float4 c4 = *(float4*)(cpt + f0);
            float4 o4;
            unsigned short hh[4];
#pragma unroll
            for (int e = 0; e < 4; ++e) {
                int f = f0 + e;
                float vi = (&zi.x)[e] + (&xi.x)[e] + bs[f];
                float vf = (&zf.x)[e] + (&xf.x)[e] + bs[64 + f];
                float vc = (&zc.x)[e] + (&xc.x)[e] + bs[128 + f];
                float vo = (&zo.x)[e] + (&xo.x)[e] + bs[192 + f];
                float ig = __saturatef(fmaf(0.2f, vi, 0.5f));
                float fg = __saturatef(fmaf(0.2f, vf, 0.5f));
                float og = __saturatef(fmaf(0.2f, vo, 0.5f));
                float cn = fmaf(fg, (&c4.x)[e], ig * tanhf(vc));
                (&c4.x)[e] = cn;
                float hv = og * tanhf(cn);
                (&o4.x)[e] = hv + (&res.x)[e];
                hh[e] = __half_as_ushort(__float2half_rn(hv));
            }
            *(float4*)(cpt + f0) = c4;
            *(float4*)(op + f0)  = o4;
            uint2 phv = make_uint2((uint32_t)hh[0] | ((uint32_t)hh[1] << 16),
                                   (uint32_t)hh[2] | ((uint32_t)hh[3] << 16));
            *(uint2*)(ho + f0) = phv;
        }
    }
}

// ---------------------------------------------------------------------------
extern "C" void kernel_launch(void* const* d_in, const int* in_sizes, int n_in,
                              void* d_out, int out_size)
{
    const float* x  = (const float*)d_in[0];
    const float* Wx = (const float*)d_in[1];
    const float* Wh = (const float*)d_in[2];
    const float* b  = (const float*)d_in[3];
    const float* Wp = (const float*)d_in[4];
    const float* bp = (const float*)d_in[5];
    float* out = (float*)d_out;

    cudaFuncSetAttribute(step_kernel,
                         cudaFuncAttributeMaxDynamicSharedMemorySize, SM_TOTAL);
    cudaFuncSetAttribute(xconv_kernel,
                         cudaFuncAttributeMaxDynamicSharedMemorySize, XC_SMEM);

    zero_kernel<<<(NTOT + 255) / 256, 256>>>();
    pad_x_kernel<<<(int)((XTOT + 255) / 256), 256>>>(x);
    prep_w_kernel<<<(36864 + 18432 + 255) / 256, 256>>>(Wx, Wh);

    dim3 xgrid(NSTRIP, BBATCH * TT);
    xconv_kernel<<<xgrid, 512, XC_SMEM>>>();

    dim3 grid(NSTRIP, BBATCH);
    for (int t = 0; t < TT; ++t)
        step_kernel<<<grid, 512, SM_TOTAL>>>(b, Wp, bp, x, out, t);
}